// round 9
// baseline (speedup 1.0000x reference)
#include <cuda_runtime.h>

#define Bg 256
#define Nn 128
#define Dd 128
#define Ll 32
#define Ee 262144
#define BNt 32768
#define Pp 8128
#define MW 256   // mask words per graph

__device__ float         g_z[BNt * Ll];       // 4 MB latents
__device__ unsigned      g_mask[Bg * MW];     // per-graph edge bitmask
__device__ int           g_deg[BNt];
__device__ int           g_off[BNt];
__device__ int           g_cur[BNt];          // fill cursor; ends as row end
__device__ unsigned char g_adj[2 * Ee];       // local neighbor ids
__device__ float         g_acc[2];            // [0]=sum log_probs, [1]=sum kls
__device__ int           g_is64;

// packed fp32 helpers ------------------------------------------------------
__device__ __forceinline__ void ffma2(unsigned long long& d,
                                      unsigned long long a, unsigned long long b) {
    asm("fma.rn.f32x2 %0, %1, %2, %3;" : "=l"(d) : "l"(a), "l"(b), "l"(d));
}
__device__ __forceinline__ float2 unpack2(unsigned long long v) {
    float lo, hi;
    asm("mov.b64 {%0, %1}, %2;" : "=f"(lo), "=f"(hi) : "l"(v));
    return make_float2(lo, hi);
}
__device__ __forceinline__ unsigned long long dup2(float x) {
    unsigned long long r; unsigned u = __float_as_uint(x);
    asm("mov.b64 %0, {%1, %1};" : "=l"(r) : "r"(u));
    return r;
}

// ---------------------------------------------------------------------------
__global__ void k_init(const void* ei) {
    int i = blockIdx.x * blockDim.x + threadIdx.x;
    int stride = gridDim.x * blockDim.x;
    for (int j = i; j < Bg * MW; j += stride) g_mask[j] = 0u;
    for (int j = i; j < BNt; j += stride) g_deg[j] = 0;
    if (i < 2) g_acc[i] = 0.f;
    if (i == 0) {
        const int* e32 = (const int*)ei;
        int all0 = 1;
        #pragma unroll
        for (int t = 0; t < 32; t++) all0 &= (e32[2 * t + 1] == 0);
        g_is64 = all0;
    }
}

__device__ __forceinline__ void load_edge(const void* ei, int e, int& s, int& d) {
    if (g_is64) {
        s = (int)((const long long*)ei)[e];
        d = (int)((const long long*)ei)[Ee + e];
    } else {
        s = ((const int*)ei)[e];
        d = ((const int*)ei)[Ee + e];
    }
}

// degree count + target bitmask
__global__ void k_count(const void* __restrict__ ei) {
    int e = blockIdx.x * blockDim.x + threadIdx.x;
    if (e >= Ee) return;
    int s, d; load_edge(ei, e, s, d);
    atomicAdd(&g_deg[s], 1);
    atomicAdd(&g_deg[d], 1);
    int li = s & (Nn - 1), lj = d & (Nn - 1), b = s >> 7;
    int p = li * (2 * Nn - li - 1) / 2 + (lj - li - 1);
    atomicOr(&g_mask[b * MW + (p >> 5)], 1u << (p & 31));
}

// exclusive scan of 32768 degrees, single CTA of 1024 threads (32 elems each)
__global__ void k_scan() {
    __shared__ int wsum[32];
    const int tid = threadIdx.x;
    int local[32];
    const int4* dv = (const int4*)g_deg;
    int s = 0;
    #pragma unroll
    for (int j = 0; j < 8; j++) {
        int4 v = dv[tid * 8 + j];
        local[j * 4 + 0] = v.x; local[j * 4 + 1] = v.y;
        local[j * 4 + 2] = v.z; local[j * 4 + 3] = v.w;
        s += v.x + v.y + v.z + v.w;
    }
    int lane = tid & 31, w = tid >> 5;
    int pre = s;
    #pragma unroll
    for (int o = 1; o < 32; o <<= 1) {
        int n = __shfl_up_sync(0xffffffffu, pre, o);
        if (lane >= o) pre += n;
    }
    if (lane == 31) wsum[w] = pre;
    __syncthreads();
    if (w == 0) {
        int v = wsum[lane];
        #pragma unroll
        for (int o = 1; o < 32; o <<= 1) {
            int n = __shfl_up_sync(0xffffffffu, v, o);
            if (lane >= o) v += n;
        }
        wsum[lane] = v;
    }
    __syncthreads();
    int run = pre - s + (w > 0 ? wsum[w - 1] : 0);
    #pragma unroll
    for (int e = 0; e < 32; e++) {
        g_off[tid * 32 + e] = run;
        g_cur[tid * 32 + e] = run;
        run += local[e];
    }
}

// adjacency fill (local 7-bit ids)
__global__ void k_fill(const void* __restrict__ ei) {
    int e = blockIdx.x * blockDim.x + threadIdx.x;
    if (e >= Ee) return;
    int s, d; load_edge(ei, e, s, d);
    int p1 = atomicAdd(&g_cur[s], 1); g_adj[p1] = (unsigned char)(d & 127);
    int p2 = atomicAdd(&g_cur[d], 1); g_adj[p2] = (unsigned char)(s & 127);
}

// block reduce over NT threads (NT/32 warps)
template <int NW>
__device__ __forceinline__ float block_reduce(float v) {
    __shared__ float sred[NW];
    int lane = threadIdx.x & 31, w = threadIdx.x >> 5;
    #pragma unroll
    for (int o = 16; o; o >>= 1) v += __shfl_down_sync(0xffffffffu, v, o);
    if (lane == 0) sred[w] = v;
    __syncthreads();
    v = (threadIdx.x < NW) ? sred[threadIdx.x] : 0.f;
    if (w == 0) {
        #pragma unroll
        for (int o = NW / 2; o; o >>= 1) v += __shfl_down_sync(0xffffffffu, v, o);
    }
    return v;  // valid in thread 0
}

// ---------------------------------------------------------------------------
// fused encoder: CTA = one graph (128 nodes), 512 threads.
// smem: shA (x tile -> then W1^T swizzled) | shT (x+agg -> then Wmu/Wls) | shH
// ---------------------------------------------------------------------------
__global__ void __launch_bounds__(512)
k_enc(const float* __restrict__ x, const float* __restrict__ W1,
      const float* __restrict__ b1, const float* __restrict__ Wmu,
      const float* __restrict__ bmu, const float* __restrict__ Wls,
      const float* __restrict__ bls, const float* __restrict__ eps) {
    extern __shared__ float sm[];
    float* shA = sm;             // 16384 floats (64KB)
    float* shT = sm + 16384;     // 16384 floats
    float* shH = sm + 32768;     // 16384 floats
    const int tid = threadIdx.x;
    const int b = blockIdx.x;
    const int lane = tid & 31;

    // 1) load graph x tile [128][128]
    {
        const float4* xg = (const float4*)(x + (size_t)b * Nn * Dd);
        float4* a4 = (float4*)shA;
        for (int i = tid; i < 4096; i += 512) a4[i] = xg[i];
    }
    __syncthreads();

    // 2) gather: warp per node (16 warps x 8 nodes): T[n] = x[n] + sum_nbr x[nbr]
    {
        const float4* a4 = (const float4*)shA;
        float4* t4 = (float4*)shT;
        int wi = tid >> 5;
        for (int t = 0; t < 8; t++) {
            int n = wi * 8 + t;
            int v = b * Nn + n;
            int o0 = g_off[v], cnt = g_cur[v] - o0;
            float4 acc = a4[n * 32 + lane];
            for (int base = 0; base < cnt; base += 32) {
                int nb_l = 0;
                if (base + lane < cnt) nb_l = g_adj[o0 + base + lane];
                int m = min(32, cnt - base);
                for (int k = 0; k < m; k++) {
                    int nb = __shfl_sync(0xffffffffu, nb_l, k);
                    float4 xv = a4[nb * 32 + lane];
                    acc.x += xv.x; acc.y += xv.y; acc.z += xv.z; acc.w += xv.w;
                }
            }
            t4[n * 32 + lane] = acc;
        }
    }
    __syncthreads();

    // 3) transpose W1 into shA: element (k,c) -> row c, f4 group ((k>>2)+(c>>2))&31
    {
        const float4* wg = (const float4*)W1;
        for (int i = tid; i < 4096; i += 512) {
            float4 v = wg[i];
            int k = i >> 5, c4 = (i & 31) * 4;
            float vv[4] = {v.x, v.y, v.z, v.w};
            #pragma unroll
            for (int m = 0; m < 4; m++) {
                int c = c4 + m;
                int g4 = ((k >> 2) + (c >> 2)) & 31;
                shA[(c * 32 + g4) * 4 + (k & 3)] = vv[m];
            }
        }
    }
    __syncthreads();

    // 4) phase1 GEMM: H = relu(T @ W1 + b1), f32x2 paired along k
    {
        const int tx = tid & 31;          // f4 col group -> cols 4tx..4tx+3
        const int rg = (tid >> 5) * 8;    // 8 rows per thread
        const ulonglong2* tA = (const ulonglong2*)shA;
        const ulonglong2* tT = (const ulonglong2*)shT;
        unsigned long long acc[8][4];
        #pragma unroll
        for (int i = 0; i < 8; i++)
            #pragma unroll
            for (int c = 0; c < 4; c++) acc[i][c] = 0ull;

        for (int k4 = 0; k4 < 32; k4++) {
            ulonglong2 w2[4];
            int gp = (k4 + tx) & 31;
            #pragma unroll
            for (int cc = 0; cc < 4; cc++) w2[cc] = tA[(4 * tx + cc) * 32 + gp];
            #pragma unroll
            for (int i = 0; i < 8; i++) {
                ulonglong2 a2 = tT[(rg + i) * 32 + k4];
                #pragma unroll
                for (int cc = 0; cc < 4; cc++) {
                    ffma2(acc[i][cc], a2.x, w2[cc].x);
                    ffma2(acc[i][cc], a2.y, w2[cc].y);
                }
            }
        }
        float4 bb = *(const float4*)(b1 + tx * 4);
        float bv[4] = {bb.x, bb.y, bb.z, bb.w};
        float4* h4 = (float4*)shH;
        #pragma unroll
        for (int i = 0; i < 8; i++) {
            float hv[4];
            #pragma unroll
            for (int cc = 0; cc < 4; cc++) {
                float2 p = unpack2(acc[i][cc]);
                hv[cc] = fmaxf(p.x + p.y + bv[cc], 0.f);
            }
            h4[(rg + i) * 32 + tx] = make_float4(hv[0], hv[1], hv[2], hv[3]);
        }
    }
    __syncthreads();

    // 5) load interleaved (Wmu,Wls) into shT region
    {
        float2* wml = (float2*)shT;
        for (int i = tid; i < 4096; i += 512)
            wml[i] = make_float2(Wmu[i], Wls[i]);
    }
    __syncthreads();

    // 6) phase2: mu/ls paired in f32x2 halves; z, KL
    float klp = 0.f;
    {
        const int l = tid & 31;
        const int rg = (tid >> 5) * 8;
        const unsigned long long* wml = (const unsigned long long*)shT;
        unsigned long long acc[8];
        #pragma unroll
        for (int i = 0; i < 8; i++) acc[i] = 0ull;
        for (int k = 0; k < 128; k++) {
            unsigned long long w2 = wml[k * 32 + l];
            #pragma unroll
            for (int i = 0; i < 8; i++) {
                float h = shH[(rg + i) * 128 + k];
                ffma2(acc[i], dup2(h), w2);
            }
        }
        float bm = bmu[l], bl = bls[l];
        #pragma unroll
        for (int i = 0; i < 8; i++) {
            int row = b * Nn + rg + i;
            float2 p = unpack2(acc[i]);
            float m = p.x + bm;
            float s = p.y + bl;
            float st = __expf(s);
            g_z[row * Ll + l] = m + st * eps[row * Ll + l];
            klp += 0.5f * (st * st + m * m - 1.f - 2.f * s);
        }
    }
    float tot = block_reduce<16>(klp);
    if (tid == 0) atomicAdd(&g_acc[1], tot);
}

// ---------------------------------------------------------------------------
// decoder: CTA = graph, 512 threads, f32x2 gram + fast softplus
// smem z layout: row n = 8 f4 groups, group k4 stored at ((k4 + (n>>3)) & 7)
// ---------------------------------------------------------------------------
__global__ void __launch_bounds__(512) k_dec() {
    __shared__ float    shZ[Nn * 32];
    __shared__ unsigned shM[MW];
    const int tid = threadIdx.x;
    const int b = blockIdx.x;

    {
        const float4* zg = (const float4*)(g_z + (size_t)b * Nn * Ll);
        float4* z4 = (float4*)shZ;
        for (int j = tid; j < 1024; j += 512) {
            int n = j >> 3, k4 = j & 7;
            z4[n * 8 + ((k4 + (n >> 3)) & 7)] = zg[j];
        }
        for (int i = tid; i < MW; i += 512) shM[i] = g_mask[b * MW + i];
    }
    __syncthreads();

    const int tx = tid & 15, ty = tid >> 4;
    const int r0 = ty * 4, c0 = tx * 8;
    const int rota = ty >> 1;
    const ulonglong2* z2 = (const ulonglong2*)shZ;

    unsigned long long acc[4][8];
    #pragma unroll
    for (int i = 0; i < 4; i++)
        #pragma unroll
        for (int j = 0; j < 8; j++) acc[i][j] = 0ull;

    #pragma unroll
    for (int k4 = 0; k4 < 8; k4++) {
        ulonglong2 bb[8];
        int gb = (k4 + tx) & 7;
        #pragma unroll
        for (int j = 0; j < 8; j++) bb[j] = z2[(c0 + j) * 8 + gb];
        int ga = (k4 + rota) & 7;
        #pragma unroll
        for (int i = 0; i < 4; i++) {
            ulonglong2 a2 = z2[(r0 + i) * 8 + ga];
            #pragma unroll
            for (int j = 0; j < 8; j++) {
                ffma2(acc[i][j], a2.x, bb[j].x);
                ffma2(acc[i][j], a2.y, bb[j].y);
            }
        }
    }

    float lp = 0.f;
    #pragma unroll
    for (int i = 0; i < 4; i++) {
        int r = r0 + i;
        #pragma unroll
        for (int j = 0; j < 8; j++) {
            int cc = c0 + j;
            if (r < cc) {
                float2 p = unpack2(acc[i][j]);
                float v = p.x + p.y;
                int pi = r * (2 * Nn - r - 1) / 2 + (cc - r - 1);
                bool t = (shM[pi >> 5] >> (pi & 31)) & 1u;
                float sp = fmaxf(v, 0.f) + __logf(1.f + __expf(-fabsf(v)));
                lp += (t ? v : 0.f) - sp;
            }
        }
    }
    float tot = block_reduce<16>(lp);
    if (tid == 0) atomicAdd(&g_acc[0], tot);
}

// ---------------------------------------------------------------------------
__global__ void k_fin(float* out) {
    out[0] = (g_acc[1] - g_acc[0]) * (1.f / (float)Bg);
}

extern "C" void kernel_launch(void* const* d_in, const int* in_sizes, int n_in,
                              void* d_out, int out_size) {
    const float* x   = (const float*)d_in[0];
    const void*  ei  = d_in[1];
    const float* eps = (const float*)d_in[3];
    const float* W1  = (const float*)d_in[4];
    const float* b1  = (const float*)d_in[5];
    const float* Wmu = (const float*)d_in[6];
    const float* bmu = (const float*)d_in[7];
    const float* Wls = (const float*)d_in[8];
    const float* bls = (const float*)d_in[9];

    k_init<<<256, 256>>>(ei);
    k_count<<<Ee / 256, 256>>>(ei);
    k_scan<<<1, 1024>>>();
    k_fill<<<Ee / 256, 256>>>(ei);
    cudaFuncSetAttribute(k_enc, cudaFuncAttributeMaxDynamicSharedMemorySize, 196608);
    k_enc<<<Bg, 512, 196608>>>(x, W1, b1, Wmu, bmu, Wls, bls, eps);
    k_dec<<<Bg, 512>>>();
    k_fin<<<1, 1>>>((float*)d_out);
}